// round 5
// baseline (speedup 1.0000x reference)
#include <cuda_runtime.h>
#include <math.h>

#define BB 4
#define SS 2048
#define DD 1024
#define HH 16
#define HDIM 64
#define MM (BB*SS)   /* 8192 */

// Scratch (device globals — no allocations allowed)
__device__ float g_Q [BB*SS*DD];
__device__ float g_K [BB*SS*DD];
__device__ float g_V [BB*SS*DD];
__device__ float g_AO[BB*SS*DD];

// ---------------------------------------------------------------------------
// C[M,N] = A[M,K] * W[N,K]^T (+ bias). Row-major everywhere.
// 128x128 block tile, BK=8, 256 threads, 8x8 micro-tile per thread.
// ---------------------------------------------------------------------------
__global__ __launch_bounds__(256) void sgemm_nt(
    const float* __restrict__ A,
    const float* __restrict__ W,
    float* __restrict__ C,
    const float* __restrict__ bias,
    int M, int N, int K)
{
    __shared__ float As[8][132];
    __shared__ float Bs[8][132];

    const int tid = threadIdx.x;
    const int tx  = tid & 15;        // 0..15 -> n micro-tile
    const int ty  = tid >> 4;        // 0..15 -> m micro-tile
    const int m0  = blockIdx.y * 128;
    const int n0  = blockIdx.x * 128;

    const int lr = tid >> 1;         // 0..127 row of tile to load
    const int lk = (tid & 1) * 4;    // 0 or 4

    const float* Ap = A + (size_t)(m0 + lr) * K + lk;
    const float* Wp = W + (size_t)(n0 + lr) * K + lk;

    float acc[8][8];
#pragma unroll
    for (int i = 0; i < 8; i++)
#pragma unroll
        for (int j = 0; j < 8; j++) acc[i][j] = 0.f;

    for (int k0 = 0; k0 < K; k0 += 8) {
        float4 av = *(const float4*)(Ap + k0);
        float4 bv = *(const float4*)(Wp + k0);
        __syncthreads();                       // previous compute done
        As[lk + 0][lr] = av.x; As[lk + 1][lr] = av.y;
        As[lk + 2][lr] = av.z; As[lk + 3][lr] = av.w;
        Bs[lk + 0][lr] = bv.x; Bs[lk + 1][lr] = bv.y;
        Bs[lk + 2][lr] = bv.z; Bs[lk + 3][lr] = bv.w;
        __syncthreads();                       // tiles visible
#pragma unroll
        for (int kk = 0; kk < 8; kk++) {
            float a[8], b[8];
            *(float4*)(a)     = *(const float4*)&As[kk][ty * 8];
            *(float4*)(a + 4) = *(const float4*)&As[kk][ty * 8 + 4];
            *(float4*)(b)     = *(const float4*)&Bs[kk][tx * 8];
            *(float4*)(b + 4) = *(const float4*)&Bs[kk][tx * 8 + 4];
#pragma unroll
            for (int i = 0; i < 8; i++)
#pragma unroll
                for (int j = 0; j < 8; j++)
                    acc[i][j] = fmaf(a[i], b[j], acc[i][j]);
        }
    }

    float bb[8];
#pragma unroll
    for (int j = 0; j < 8; j++)
        bb[j] = bias ? bias[n0 + tx * 8 + j] : 0.f;

#pragma unroll
    for (int i = 0; i < 8; i++) {
        float* Cp = C + (size_t)(m0 + ty * 8 + i) * N + n0 + tx * 8;
        float4 r0 = make_float4(acc[i][0] + bb[0], acc[i][1] + bb[1],
                                acc[i][2] + bb[2], acc[i][3] + bb[3]);
        float4 r1 = make_float4(acc[i][4] + bb[4], acc[i][5] + bb[5],
                                acc[i][6] + bb[6], acc[i][7] + bb[7]);
        *(float4*)(Cp)     = r0;
        *(float4*)(Cp + 4) = r1;
    }
}

// ---------------------------------------------------------------------------
// Flash-attention (fp32, full softmax over S=2048).
// One block = one (b, h, 64-query tile). 64 threads, 8x8 micro-tiles.
// smem: Qs (natural), KP (K swizzled / reused for P natural), VsT (V^T swizzled)
// ---------------------------------------------------------------------------
__global__ __launch_bounds__(64) void attn_kernel(
    const float* __restrict__ Q,
    const float* __restrict__ K,
    const float* __restrict__ V,
    float* __restrict__ O)
{
    __shared__ float Qs [64][64];
    __shared__ float KP [64][64];
    __shared__ float VsT[64][64];

    const int tid = threadIdx.x;
    const int tx  = tid & 7;        // 0..7
    const int ty  = tid >> 3;       // 0..7
    const int qt  = blockIdx.x;     // query tile 0..31
    const int bh  = blockIdx.y;     // 0..63
    const int b   = bh >> 4;
    const int h   = bh & 15;

    const float* Qg = Q + ((size_t)b * SS + qt * 64) * DD + h * HDIM;
    const float* Kg = K + ((size_t)b * SS) * DD + h * HDIM;
    const float* Vg = V + ((size_t)b * SS) * DD + h * HDIM;

    // load Q tile (natural layout; reads are tx-broadcast)
#pragma unroll
    for (int it = 0; it < 16; it++) {
        int idx = it * 64 + tid;
        int r = idx >> 4, d4 = (idx & 15) << 2;
        *(float4*)&Qs[r][d4] = *(const float4*)(Qg + (size_t)r * DD + d4);
    }

    float o[8][8];
    float m[8], l[8];
#pragma unroll
    for (int i = 0; i < 8; i++) {
        m[i] = -1e30f; l[i] = 0.f;
#pragma unroll
        for (int j = 0; j < 8; j++) o[i][j] = 0.f;
    }
    const int swz = tx << 2;   // XOR swizzle constant for this thread's rows

    __syncthreads();

    for (int t = 0; t < SS / 64; t++) {
        // ---- load K tile (swizzled rows) + V tile transposed (swizzled cols)
#pragma unroll
        for (int it = 0; it < 16; it++) {
            int idx = it * 64 + tid;
            int c = idx >> 4, d4 = (idx & 15) << 2;
            float4 kv = *(const float4*)(Kg + (size_t)(t * 64 + c) * DD + d4);
            *(float4*)&KP[c][d4 ^ ((c >> 3) << 2)] = kv;
            float4 vv = *(const float4*)(Vg + (size_t)(t * 64 + c) * DD + d4);
            VsT[d4 + 0][c ^ (((d4 + 0) >> 3) << 2)] = vv.x;
            VsT[d4 + 1][c ^ (((d4 + 1) >> 3) << 2)] = vv.y;
            VsT[d4 + 2][c ^ (((d4 + 2) >> 3) << 2)] = vv.z;
            VsT[d4 + 3][c ^ (((d4 + 3) >> 3) << 2)] = vv.w;
        }
        __syncthreads();

        // ---- scores: S = Q K^T (dot-product form, 8x8 per thread)
        float s[8][8];
#pragma unroll
        for (int i = 0; i < 8; i++)
#pragma unroll
            for (int j = 0; j < 8; j++) s[i][j] = 0.f;

#pragma unroll
        for (int d4 = 0; d4 < 64; d4 += 4) {
            float4 aq[8], bk[8];
#pragma unroll
            for (int i = 0; i < 8; i++)
                aq[i] = *(const float4*)&Qs[ty * 8 + i][d4];
#pragma unroll
            for (int j = 0; j < 8; j++)
                bk[j] = *(const float4*)&KP[tx * 8 + j][d4 ^ swz];
#pragma unroll
            for (int i = 0; i < 8; i++)
#pragma unroll
                for (int j = 0; j < 8; j++) {
                    s[i][j] = fmaf(aq[i].x, bk[j].x, s[i][j]);
                    s[i][j] = fmaf(aq[i].y, bk[j].y, s[i][j]);
                    s[i][j] = fmaf(aq[i].z, bk[j].z, s[i][j]);
                    s[i][j] = fmaf(aq[i].w, bk[j].w, s[i][j]);
                }
        }
        __syncthreads();   // all threads done reading KP(K)

        // ---- online softmax (rows owned by 8-lane shfl groups)
#pragma unroll
        for (int i = 0; i < 8; i++) {
            float mx = -1e30f;
#pragma unroll
            for (int j = 0; j < 8; j++) {
                s[i][j] *= 0.03125f;    // 1/sqrt(1024)
                mx = fmaxf(mx, s[i][j]);
            }
            mx = fmaxf(mx, __shfl_xor_sync(0xffffffffu, mx, 1));
            mx = fmaxf(mx, __shfl_xor_sync(0xffffffffu, mx, 2));
            mx = fmaxf(mx, __shfl_xor_sync(0xffffffffu, mx, 4));
            float mn   = fmaxf(m[i], mx);
            float corr = __expf(m[i] - mn);
            m[i] = mn;
            float rs = 0.f;
#pragma unroll
            for (int j = 0; j < 8; j++) {
                s[i][j] = __expf(s[i][j] - mn);
                rs += s[i][j];
            }
            rs += __shfl_xor_sync(0xffffffffu, rs, 1);
            rs += __shfl_xor_sync(0xffffffffu, rs, 2);
            rs += __shfl_xor_sync(0xffffffffu, rs, 4);
            l[i] = l[i] * corr + rs;
#pragma unroll
            for (int j = 0; j < 8; j++) o[i][j] *= corr;
            // store P (natural layout) into KP region
            *(float4*)&KP[ty * 8 + i][tx * 8] =
                make_float4(s[i][0], s[i][1], s[i][2], s[i][3]);
            *(float4*)&KP[ty * 8 + i][tx * 8 + 4] =
                make_float4(s[i][4], s[i][5], s[i][6], s[i][7]);
        }
        __syncthreads();   // P visible

        // ---- O += P V  (dot-product form over keys)
#pragma unroll
        for (int k4 = 0; k4 < 64; k4 += 4) {
            float4 pp[8], vv[8];
#pragma unroll
            for (int i = 0; i < 8; i++)
                pp[i] = *(const float4*)&KP[ty * 8 + i][k4];
#pragma unroll
            for (int j = 0; j < 8; j++)
                vv[j] = *(const float4*)&VsT[tx * 8 + j][k4 ^ swz];
#pragma unroll
            for (int i = 0; i < 8; i++)
#pragma unroll
                for (int j = 0; j < 8; j++) {
                    o[i][j] = fmaf(pp[i].x, vv[j].x, o[i][j]);
                    o[i][j] = fmaf(pp[i].y, vv[j].y, o[i][j]);
                    o[i][j] = fmaf(pp[i].z, vv[j].z, o[i][j]);
                    o[i][j] = fmaf(pp[i].w, vv[j].w, o[i][j]);
                }
        }
        __syncthreads();   // done reading KP/VsT before next tile's loads
    }

    // ---- normalize + write [b, s, h*64 + hd]
    float* Og = O + ((size_t)b * SS + qt * 64) * DD + h * HDIM;
#pragma unroll
    for (int i = 0; i < 8; i++) {
        float inv = 1.f / l[i];
        float* Op = Og + (size_t)(ty * 8 + i) * DD + tx * 8;
        *(float4*)(Op) = make_float4(o[i][0] * inv, o[i][1] * inv,
                                     o[i][2] * inv, o[i][3] * inv);
        *(float4*)(Op + 4) = make_float4(o[i][4] * inv, o[i][5] * inv,
                                         o[i][6] * inv, o[i][7] * inv);
    }
}

// ---------------------------------------------------------------------------
extern "C" void kernel_launch(void* const* d_in, const int* in_sizes, int n_in,
                              void* d_out, int out_size)
{
    const float* q  = (const float*)d_in[0];
    const float* k  = (const float*)d_in[1];
    const float* v  = (const float*)d_in[2];
    const float* Wq = (const float*)d_in[3];
    const float* Wk = (const float*)d_in[4];
    const float* Wv = (const float*)d_in[5];
    const float* Wo = (const float*)d_in[6];
    const float* bo = (const float*)d_in[7];
    float* out = (float*)d_out;

    void *pQ, *pK, *pV, *pAO;
    cudaGetSymbolAddress(&pQ,  g_Q);
    cudaGetSymbolAddress(&pK,  g_K);
    cudaGetSymbolAddress(&pV,  g_V);
    cudaGetSymbolAddress(&pAO, g_AO);

    dim3 gridG(DD / 128, MM / 128);   // (8, 64)
    sgemm_nt<<<gridG, 256>>>(q, Wq, (float*)pQ, nullptr, MM, DD, DD);
    sgemm_nt<<<gridG, 256>>>(k, Wk, (float*)pK, nullptr, MM, DD, DD);
    sgemm_nt<<<gridG, 256>>>(v, Wv, (float*)pV, nullptr, MM, DD, DD);

    dim3 gridA(SS / 64, BB * HH);     // (32, 64)
    attn_kernel<<<gridA, 64>>>((const float*)pQ, (const float*)pK,
                               (const float*)pV, (float*)pAO);

    sgemm_nt<<<gridG, 256>>>((const float*)pAO, Wo, out, bo, MM, DD, DD);
}

// round 8
// speedup vs baseline: 1.9889x; 1.9889x over previous
#include <cuda_runtime.h>
#include <cstdint>
#include <math.h>

#define BB 4
#define SS 2048
#define DD 1024
#define HH 16
#define HDIM 64
#define MM (BB*SS)   /* 8192 */

// Scratch (device globals — no allocations allowed)
__device__ float g_Q [BB*SS*DD];
__device__ float g_K [BB*SS*DD];
__device__ float g_V [BB*SS*DD];
__device__ float g_AO[BB*SS*DD];

// ---------------------------------------------------------------------------
// tf32 helpers (plain PTX ISA — no sm_103a-gated features)
// ---------------------------------------------------------------------------
static __device__ __forceinline__ uint32_t f2tf(float x) {
    uint32_t u;
    asm("cvt.rna.tf32.f32 %0, %1;" : "=r"(u) : "f"(x));
    return u;
}

static __device__ __forceinline__ void mma8(float* c, const uint32_t* a,
                                            const uint32_t* b) {
    asm volatile(
        "mma.sync.aligned.m16n8k8.row.col.f32.tf32.tf32.f32 "
        "{%0,%1,%2,%3}, {%4,%5,%6,%7}, {%8,%9}, {%0,%1,%2,%3};"
        : "+f"(c[0]), "+f"(c[1]), "+f"(c[2]), "+f"(c[3])
        : "r"(a[0]), "r"(a[1]), "r"(a[2]), "r"(a[3]), "r"(b[0]), "r"(b[1]));
}

// ---------------------------------------------------------------------------
// tf32 mma.sync GEMM: C[M,N] = alpha * A[M,K] * W[N,K]^T (+ bias)
// CTA 128x128, 256 threads (8 warps x 32x64 tiles), K-chunk 32, single smem
// buffer + register prefetch. LDA=36 words -> conflict-free fragment LDS.
// M=8192, N=K=1024 (DD) hardcoded.
// ---------------------------------------------------------------------------
#define LDA 36

__global__ __launch_bounds__(256) void gemm_mma(
    const float* __restrict__ A, const float* __restrict__ W,
    float* __restrict__ C, const float* __restrict__ bias, float alpha)
{
    __shared__ uint32_t As[128 * LDA];
    __shared__ uint32_t Ws[128 * LDA];

    const int tid  = threadIdx.x;
    const int w    = tid >> 5;
    const int lane = tid & 31;
    const int ly   = lane >> 2;         // 0..7
    const int lx   = lane & 3;          // 0..3
    const int m0   = blockIdx.y * 128;
    const int n0   = blockIdx.x * 128;
    const int wm   = (w & 3) * 32;      // warp m-offset in tile
    const int wn   = (w >> 2) * 64;     // warp n-offset in tile

    // global load mapping: thread covers rows lrow+32i (i=0..3), float4 col lc4
    const int lrow = tid >> 3;          // 0..31
    const int lc4  = tid & 7;           // 0..7
    const float* Ap = A + (size_t)(m0 + lrow) * DD + lc4 * 4;
    const float* Wp = W + (size_t)(n0 + lrow) * DD + lc4 * 4;

    float acc[2][8][4];
#pragma unroll
    for (int i = 0; i < 2; i++)
#pragma unroll
        for (int j = 0; j < 8; j++)
#pragma unroll
            for (int r = 0; r < 4; r++) acc[i][j][r] = 0.f;

    float4 ra[4], rw[4];
#pragma unroll
    for (int i = 0; i < 4; i++) {                       // prefetch chunk 0
        ra[i] = *(const float4*)(Ap + (size_t)(32 * i) * DD);
        rw[i] = *(const float4*)(Wp + (size_t)(32 * i) * DD);
    }
#pragma unroll
    for (int i = 0; i < 4; i++) {                       // cvt+store chunk 0
        uint32_t* pa = &As[(lrow + 32 * i) * LDA + lc4 * 4];
        pa[0] = f2tf(ra[i].x); pa[1] = f2tf(ra[i].y);
        pa[2] = f2tf(ra[i].z); pa[3] = f2tf(ra[i].w);
        uint32_t* pw = &Ws[(lrow + 32 * i) * LDA + lc4 * 4];
        pw[0] = f2tf(rw[i].x); pw[1] = f2tf(rw[i].y);
        pw[2] = f2tf(rw[i].z); pw[3] = f2tf(rw[i].w);
    }
    __syncthreads();

    for (int kc = 0; kc < DD / 32; kc++) {
        if (kc + 1 < DD / 32) {                         // prefetch next chunk
            const float* Ap2 = Ap + (kc + 1) * 32;
            const float* Wp2 = Wp + (kc + 1) * 32;
#pragma unroll
            for (int i = 0; i < 4; i++) {
                ra[i] = *(const float4*)(Ap2 + (size_t)(32 * i) * DD);
                rw[i] = *(const float4*)(Wp2 + (size_t)(32 * i) * DD);
            }
        }

        // ---- compute current chunk (k = 32 -> 4 mma k-steps)
#pragma unroll
        for (int ks = 0; ks < 4; ks++) {
            const int k0 = ks * 8;
            uint32_t af[2][4], bf[8][2];
#pragma unroll
            for (int i = 0; i < 2; i++) {
                int base = (wm + i * 16 + ly) * LDA + k0 + lx;
                af[i][0] = As[base];
                af[i][1] = As[base + 8 * LDA];
                af[i][2] = As[base + 4];
                af[i][3] = As[base + 8 * LDA + 4];
            }
#pragma unroll
            for (int j = 0; j < 8; j++) {
                int base = (wn + j * 8 + ly) * LDA + k0 + lx;
                bf[j][0] = Ws[base];
                bf[j][1] = Ws[base + 4];
            }
#pragma unroll
            for (int i = 0; i < 2; i++)
#pragma unroll
                for (int j = 0; j < 8; j++)
                    mma8(acc[i][j], af[i], bf[j]);
        }
        __syncthreads();                                // done reading smem

        if (kc + 1 < DD / 32) {
#pragma unroll
            for (int i = 0; i < 4; i++) {
                uint32_t* pa = &As[(lrow + 32 * i) * LDA + lc4 * 4];
                pa[0] = f2tf(ra[i].x); pa[1] = f2tf(ra[i].y);
                pa[2] = f2tf(ra[i].z); pa[3] = f2tf(ra[i].w);
                uint32_t* pw = &Ws[(lrow + 32 * i) * LDA + lc4 * 4];
                pw[0] = f2tf(rw[i].x); pw[1] = f2tf(rw[i].y);
                pw[2] = f2tf(rw[i].z); pw[3] = f2tf(rw[i].w);
            }
            __syncthreads();                            // stores visible
        }
    }

    // ---- epilogue: c0,c1 at (row, 2lx), c2,c3 at (row+8, 2lx)
#pragma unroll
    for (int i = 0; i < 2; i++) {
        int row = m0 + wm + i * 16 + ly;
#pragma unroll
        for (int j = 0; j < 8; j++) {
            int col = n0 + wn + j * 8 + lx * 2;
            float b0 = bias ? bias[col]     : 0.f;
            float b1 = bias ? bias[col + 1] : 0.f;
            float2 v0 = make_float2(acc[i][j][0] * alpha + b0,
                                    acc[i][j][1] * alpha + b1);
            float2 v1 = make_float2(acc[i][j][2] * alpha + b0,
                                    acc[i][j][3] * alpha + b1);
            *(float2*)(C + (size_t)row * DD + col)       = v0;
            *(float2*)(C + (size_t)(row + 8) * DD + col) = v1;
        }
    }
}

// ---------------------------------------------------------------------------
// Flash-attention (fp32). One block = one (b, h, 64-query tile).
// 128 threads: ty(8) x tx(16); per-thread 8 queries x 4 keys / 4 out-cols.
// Scale 1/sqrt(D) is pre-folded into the Q projection.
// ---------------------------------------------------------------------------
__global__ __launch_bounds__(128, 4) void attn_kernel(
    const float* __restrict__ Q,
    const float* __restrict__ K,
    const float* __restrict__ V,
    float* __restrict__ O)
{
    __shared__ float Qs [64][64];
    __shared__ float KP [64][64];
    __shared__ float VsT[64][64];

    const int tid = threadIdx.x;
    const int tx  = tid & 15;       // 0..15
    const int ty  = tid >> 4;       // 0..7
    const int qt  = blockIdx.x;     // 0..31
    const int bh  = blockIdx.y;     // 0..63
    const int b   = bh >> 4;
    const int h   = bh & 15;

    const float* Qg = Q + ((size_t)b * SS + qt * 64) * DD + h * HDIM;
    const float* Kg = K + ((size_t)b * SS) * DD + h * HDIM;
    const float* Vg = V + ((size_t)b * SS) * DD + h * HDIM;

#pragma unroll
    for (int it = 0; it < 8; it++) {
        int idx = it * 128 + tid;
        int r = idx >> 4, d4 = (idx & 15) << 2;
        *(float4*)&Qs[r][d4] = *(const float4*)(Qg + (size_t)r * DD + d4);
    }

    float o[8][4], m[8], l[8];
#pragma unroll
    for (int i = 0; i < 8; i++) {
        m[i] = -1e30f; l[i] = 0.f;
#pragma unroll
        for (int j = 0; j < 4; j++) o[i][j] = 0.f;
    }
    // (4*tx+j)>>3 == tx>>1 for all j in [0,4): uniform swizzle per thread
    const int swz = (tx >> 1) << 2;

    __syncthreads();

    for (int t = 0; t < SS / 64; t++) {
        // ---- load K tile (row-swizzled) + V tile transposed (col-swizzled)
#pragma unroll
        for (int it = 0; it < 8; it++) {
            int idx = it * 128 + tid;
            int c = idx >> 4, d4 = (idx & 15) << 2;
            float4 kv = *(const float4*)(Kg + (size_t)(t * 64 + c) * DD + d4);
            *(float4*)&KP[c][d4 ^ ((c >> 3) << 2)] = kv;
            float4 vv = *(const float4*)(Vg + (size_t)(t * 64 + c) * DD + d4);
            int sw = (d4 >> 3) << 2;
            VsT[d4 + 0][c ^ sw] = vv.x;
            VsT[d4 + 1][c ^ sw] = vv.y;
            VsT[d4 + 2][c ^ sw] = vv.z;
            VsT[d4 + 3][c ^ sw] = vv.w;
        }
        __syncthreads();

        // ---- scores: S = Q K^T
        float s[8][4];
#pragma unroll
        for (int i = 0; i < 8; i++)
#pragma unroll
            for (int j = 0; j < 4; j++) s[i][j] = 0.f;

#pragma unroll
        for (int d4 = 0; d4 < 64; d4 += 4) {
            float4 bk[4];
#pragma unroll
            for (int j = 0; j < 4; j++)
                bk[j] = *(const float4*)&KP[tx * 4 + j][d4 ^ swz];
#pragma unroll
            for (int i = 0; i < 8; i++) {
                float4 aq = *(const float4*)&Qs[ty * 8 + i][d4];
#pragma unroll
                for (int j = 0; j < 4; j++) {
                    s[i][j] = fmaf(aq.x, bk[j].x, s[i][j]);
                    s[i][j] = fmaf(aq.y, bk[j].y, s[i][j]);
                    s[i][j] = fmaf(aq.z, bk[j].z, s[i][j]);
                    s[i][j] = fmaf(aq.w, bk[j].w, s[i][j]);
                }
            }
        }
        __syncthreads();   // done reading K from KP

        // ---- online softmax; rows reduced over 16 tx lanes
#pragma unroll
        for (int i = 0; i < 8; i++) {
            float mx = fmaxf(fmaxf(s[i][0], s[i][1]), fmaxf(s[i][2], s[i][3]));
            mx = fmaxf(mx, __shfl_xor_sync(0xffffffffu, mx, 1));
            mx = fmaxf(mx, __shfl_xor_sync(0xffffffffu, mx, 2));
            mx = fmaxf(mx, __shfl_xor_sync(0xffffffffu, mx, 4));
            mx = fmaxf(mx, __shfl_xor_sync(0xffffffffu, mx, 8));
            float mn   = fmaxf(m[i], mx);
            float corr = __expf(m[i] - mn);
            m[i] = mn;
            float rs = 0.f;
#pragma unroll
            for (int j = 0; j < 4; j++) {
                s[i][j] = __expf(s[i][j] - mn);
                rs += s[i][j];
            }
            rs += __shfl_xor_sync(0xffffffffu, rs, 1);
            rs += __shfl_xor_sync(0xffffffffu, rs, 2);
            rs += __shfl_xor_sync(0xffffffffu, rs, 4);
            rs += __shfl_xor_sync(0xffffffffu, rs, 8);
            l[i] = l[i] * corr + rs;
#pragma unroll
            for (int j = 0; j < 4; j++) o[i][j] *= corr;
            *(float4*)&KP[ty * 8 + i][tx * 4] =
                make_float4(s[i][0], s[i][1], s[i][2], s[i][3]);
        }
        __syncthreads();   // P visible

        // ---- O += P V
#pragma unroll
        for (int k4 = 0; k4 < 64; k4 += 4) {
            float4 vv[4];
#pragma unroll
            for (int j = 0; j < 4; j++)
                vv[j] = *(const float4*)&VsT[tx * 4 + j][k4 ^ swz];
#pragma unroll
            for (int i = 0; i < 8; i++) {
                float4 pp = *(const float4*)&KP[ty * 8 + i][k4];
#pragma unroll
                for (int j = 0; j < 4; j++) {
                    o[i][j] = fmaf(pp.x, vv[j].x, o[i][j]);
                    o[i][j] = fmaf(pp.y, vv[j].y, o[i][j]);
                    o[i][j] = fmaf(pp.z, vv[j].z, o[i][j]);
                    o[i][j] = fmaf(pp.w, vv[j].w, o[i][j]);
                }
            }
        }
        __syncthreads();   // done with KP/VsT before next tile's loads
    }

    // ---- normalize + write [b, s, h*64 + hd]
    float* Og = O + ((size_t)b * SS + qt * 64) * DD + h * HDIM;
#pragma unroll
    for (int i = 0; i < 8; i++) {
        float inv = 1.f / l[i];
        *(float4*)(Og + (size_t)(ty * 8 + i) * DD + tx * 4) =
            make_float4(o[i][0] * inv, o[i][1] * inv, o[i][2] * inv, o[i][3] * inv);
    }
}

// ---------------------------------------------------------------------------
extern "C" void kernel_launch(void* const* d_in, const int* in_sizes, int n_in,
                              void* d_out, int out_size)
{
    const float* q  = (const float*)d_in[0];
    const float* k  = (const float*)d_in[1];
    const float* v  = (const float*)d_in[2];
    const float* Wq = (const float*)d_in[3];
    const float* Wk = (const float*)d_in[4];
    const float* Wv = (const float*)d_in[5];
    const float* Wo = (const float*)d_in[6];
    const float* bo = (const float*)d_in[7];
    float* out = (float*)d_out;

    void *pQ, *pK, *pV, *pAO;
    cudaGetSymbolAddress(&pQ,  g_Q);
    cudaGetSymbolAddress(&pK,  g_K);
    cudaGetSymbolAddress(&pV,  g_V);
    cudaGetSymbolAddress(&pAO, g_AO);

    dim3 gg(DD / 128, MM / 128);   // (8, 64)
    // scale 1/sqrt(D)=1/32 folded into Q projection
    gemm_mma<<<gg, 256>>>(q, Wq, (float*)pQ, nullptr, 0.03125f);
    gemm_mma<<<gg, 256>>>(k, Wk, (float*)pK, nullptr, 1.0f);
    gemm_mma<<<gg, 256>>>(v, Wv, (float*)pV, nullptr, 1.0f);

    dim3 ga(SS / 64, BB * HH);     // (32, 64)
    attn_kernel<<<ga, 128>>>((const float*)pQ, (const float*)pK,
                             (const float*)pV, (float*)pAO);

    gemm_mma<<<gg, 256>>>((const float*)pAO, Wo, out, bo, 1.0f);
}

// round 11
// speedup vs baseline: 4.3681x; 2.1962x over previous
#include <cuda_runtime.h>
#include <cstdint>
#include <math.h>

#define BB 4
#define SS 2048
#define DD 1024
#define HH 16
#define HDIM 64
#define MM (BB*SS)   /* 8192 */

// Scratch (device globals — no allocations allowed)
__device__ float g_Q [BB*SS*DD];
__device__ float g_K [BB*SS*DD];
__device__ float g_V [BB*SS*DD];
__device__ float g_AO[BB*SS*DD];

// ---------------------------------------------------------------------------
// tf32 helpers (plain PTX ISA — no sm_103a-gated features)
// ---------------------------------------------------------------------------
static __device__ __forceinline__ uint32_t f2tf(float x) {
    uint32_t u;
    asm("cvt.rna.tf32.f32 %0, %1;" : "=r"(u) : "f"(x));
    return u;
}

static __device__ __forceinline__ void mma8(float* c, const uint32_t* a,
                                            const uint32_t* b) {
    asm volatile(
        "mma.sync.aligned.m16n8k8.row.col.f32.tf32.tf32.f32 "
        "{%0,%1,%2,%3}, {%4,%5,%6,%7}, {%8,%9}, {%0,%1,%2,%3};"
        : "+f"(c[0]), "+f"(c[1]), "+f"(c[2]), "+f"(c[3])
        : "r"(a[0]), "r"(a[1]), "r"(a[2]), "r"(a[3]), "r"(b[0]), "r"(b[1]));
}

// ---------------------------------------------------------------------------
// tf32 mma.sync GEMM: C[M,N] = alpha * A[M,K] * W[N,K]^T (+ bias)
// CTA 128x128, 256 threads (8 warps x 32x64 tiles), K-chunk 32, single smem
// buffer + register prefetch. LDA=36 words -> conflict-free fragment LDS.
// M=8192, N=K=1024 (DD) hardcoded.
// ---------------------------------------------------------------------------
#define LDA 36

__global__ __launch_bounds__(256) void gemm_mma(
    const float* __restrict__ A, const float* __restrict__ W,
    float* __restrict__ C, const float* __restrict__ bias, float alpha)
{
    __shared__ uint32_t As[128 * LDA];
    __shared__ uint32_t Ws[128 * LDA];

    const int tid  = threadIdx.x;
    const int w    = tid >> 5;
    const int lane = tid & 31;
    const int ly   = lane >> 2;         // 0..7
    const int lx   = lane & 3;          // 0..3
    const int m0   = blockIdx.y * 128;
    const int n0   = blockIdx.x * 128;
    const int wm   = (w & 3) * 32;      // warp m-offset in tile
    const int wn   = (w >> 2) * 64;     // warp n-offset in tile

    const int lrow = tid >> 3;          // 0..31
    const int lc4  = tid & 7;           // 0..7
    const float* Ap = A + (size_t)(m0 + lrow) * DD + lc4 * 4;
    const float* Wp = W + (size_t)(n0 + lrow) * DD + lc4 * 4;

    float acc[2][8][4];
#pragma unroll
    for (int i = 0; i < 2; i++)
#pragma unroll
        for (int j = 0; j < 8; j++)
#pragma unroll
            for (int r = 0; r < 4; r++) acc[i][j][r] = 0.f;

    float4 ra[4], rw[4];
#pragma unroll
    for (int i = 0; i < 4; i++) {                       // prefetch chunk 0
        ra[i] = *(const float4*)(Ap + (size_t)(32 * i) * DD);
        rw[i] = *(const float4*)(Wp + (size_t)(32 * i) * DD);
    }
#pragma unroll
    for (int i = 0; i < 4; i++) {                       // cvt+store chunk 0
        uint32_t* pa = &As[(lrow + 32 * i) * LDA + lc4 * 4];
        pa[0] = f2tf(ra[i].x); pa[1] = f2tf(ra[i].y);
        pa[2] = f2tf(ra[i].z); pa[3] = f2tf(ra[i].w);
        uint32_t* pw = &Ws[(lrow + 32 * i) * LDA + lc4 * 4];
        pw[0] = f2tf(rw[i].x); pw[1] = f2tf(rw[i].y);
        pw[2] = f2tf(rw[i].z); pw[3] = f2tf(rw[i].w);
    }
    __syncthreads();

    for (int kc = 0; kc < DD / 32; kc++) {
        if (kc + 1 < DD / 32) {                         // prefetch next chunk
            const float* Ap2 = Ap + (kc + 1) * 32;
            const float* Wp2 = Wp + (kc + 1) * 32;
#pragma unroll
            for (int i = 0; i < 4; i++) {
                ra[i] = *(const float4*)(Ap2 + (size_t)(32 * i) * DD);
                rw[i] = *(const float4*)(Wp2 + (size_t)(32 * i) * DD);
            }
        }

#pragma unroll
        for (int ks = 0; ks < 4; ks++) {
            const int k0 = ks * 8;
            uint32_t af[2][4], bf[8][2];
#pragma unroll
            for (int i = 0; i < 2; i++) {
                int base = (wm + i * 16 + ly) * LDA + k0 + lx;
                af[i][0] = As[base];
                af[i][1] = As[base + 8 * LDA];
                af[i][2] = As[base + 4];
                af[i][3] = As[base + 8 * LDA + 4];
            }
#pragma unroll
            for (int j = 0; j < 8; j++) {
                int base = (wn + j * 8 + ly) * LDA + k0 + lx;
                bf[j][0] = Ws[base];
                bf[j][1] = Ws[base + 4];
            }
#pragma unroll
            for (int i = 0; i < 2; i++)
#pragma unroll
                for (int j = 0; j < 8; j++)
                    mma8(acc[i][j], af[i], bf[j]);
        }
        __syncthreads();

        if (kc + 1 < DD / 32) {
#pragma unroll
            for (int i = 0; i < 4; i++) {
                uint32_t* pa = &As[(lrow + 32 * i) * LDA + lc4 * 4];
                pa[0] = f2tf(ra[i].x); pa[1] = f2tf(ra[i].y);
                pa[2] = f2tf(ra[i].z); pa[3] = f2tf(ra[i].w);
                uint32_t* pw = &Ws[(lrow + 32 * i) * LDA + lc4 * 4];
                pw[0] = f2tf(rw[i].x); pw[1] = f2tf(rw[i].y);
                pw[2] = f2tf(rw[i].z); pw[3] = f2tf(rw[i].w);
            }
            __syncthreads();
        }
    }

#pragma unroll
    for (int i = 0; i < 2; i++) {
        int row = m0 + wm + i * 16 + ly;
#pragma unroll
        for (int j = 0; j < 8; j++) {
            int col = n0 + wn + j * 8 + lx * 2;
            float b0 = bias ? bias[col]     : 0.f;
            float b1 = bias ? bias[col + 1] : 0.f;
            float2 v0 = make_float2(acc[i][j][0] * alpha + b0,
                                    acc[i][j][1] * alpha + b1);
            float2 v1 = make_float2(acc[i][j][2] * alpha + b0,
                                    acc[i][j][3] * alpha + b1);
            *(float2*)(C + (size_t)row * DD + col)       = v0;
            *(float2*)(C + (size_t)(row + 8) * DD + col) = v1;
        }
    }
}

// ---------------------------------------------------------------------------
// Flash-attention with tf32 mma.sync.
// One block = (b, h, 64-query tile). 4 warps x 16 queries each.
// Q fragments in registers; K/V tiles in smem (stride 76 -> conflict-free
// fragment LDS); P reuses the K buffer (warp-private rows).
// Scale 1/sqrt(D) pre-folded into the Q projection.
// ---------------------------------------------------------------------------
#define AST 76   /* smem row stride (words) for attn tiles */

__global__ __launch_bounds__(128, 4) void attn_mma(
    const float* __restrict__ Q,
    const float* __restrict__ K,
    const float* __restrict__ V,
    float* __restrict__ O)
{
    __shared__ uint32_t KP[64 * AST];   // K tile, then P tile
    __shared__ uint32_t Vs[64 * AST];   // V tile

    const int tid  = threadIdx.x;
    const int w    = tid >> 5;
    const int lane = tid & 31;
    const int ly   = lane >> 2;         // 0..7
    const int lx   = lane & 3;          // 0..3
    const int qw   = w * 16;            // warp's query offset in tile
    const int qt   = blockIdx.x;        // 0..31
    const int bh   = blockIdx.y;        // 0..63
    const int b    = bh >> 4;
    const int h    = bh & 15;

    const float* Qg = Q + ((size_t)b * SS + qt * 64) * DD + h * HDIM;
    const float* Kg = K + (size_t)b * SS * DD + h * HDIM;
    const float* Vg = V + (size_t)b * SS * DD + h * HDIM;
    float*       Og = O + ((size_t)b * SS + qt * 64) * DD + h * HDIM;

    // ---- Q fragments (held in registers for the whole kernel)
    uint32_t aq[8][4];
#pragma unroll
    for (int ks = 0; ks < 8; ks++) {
        const float* qp = Qg + (size_t)(qw + ly) * DD + ks * 8 + lx;
        aq[ks][0] = f2tf(qp[0]);
        aq[ks][1] = f2tf(qp[(size_t)8 * DD]);
        aq[ks][2] = f2tf(qp[4]);
        aq[ks][3] = f2tf(qp[(size_t)8 * DD + 4]);
    }

    float o[8][4];
    float m0 = -1e30f, m1 = -1e30f, l0 = 0.f, l1 = 0.f;
#pragma unroll
    for (int j = 0; j < 8; j++)
#pragma unroll
        for (int r = 0; r < 4; r++) o[j][r] = 0.f;

    for (int t = 0; t < SS / 64; t++) {
        // ---- load K,V tiles (cvt to tf32 at store)
#pragma unroll
        for (int it = 0; it < 8; it++) {
            int idx = it * 128 + tid;
            int c = idx >> 4, d4 = (idx & 15) << 2;
            float4 kv = *(const float4*)(Kg + (size_t)(t * 64 + c) * DD + d4);
            uint4 kt = make_uint4(f2tf(kv.x), f2tf(kv.y), f2tf(kv.z), f2tf(kv.w));
            *(uint4*)&KP[c * AST + d4] = kt;
            float4 vv = *(const float4*)(Vg + (size_t)(t * 64 + c) * DD + d4);
            uint4 vt = make_uint4(f2tf(vv.x), f2tf(vv.y), f2tf(vv.z), f2tf(vv.w));
            *(uint4*)&Vs[c * AST + d4] = vt;
        }
        __syncthreads();

        // ---- S = Q K^T : rows = warp's 16 queries, cols = 64 keys
        float s[8][4];
#pragma unroll
        for (int j = 0; j < 8; j++)
#pragma unroll
            for (int r = 0; r < 4; r++) s[j][r] = 0.f;

#pragma unroll
        for (int ks = 0; ks < 8; ks++) {
#pragma unroll
            for (int j = 0; j < 8; j++) {
                uint32_t bf[2];
                int base = (ly + 8 * j) * AST + 8 * ks + lx;
                bf[0] = KP[base];
                bf[1] = KP[base + 4];
                mma8(s[j], aq[ks], bf);
            }
        }
        __syncthreads();   // all warps done reading K before P overwrites

        // ---- online softmax (rows ly / ly+8; 4-lane quad owns a row)
        float mx0 = -1e30f, mx1 = -1e30f;
#pragma unroll
        for (int j = 0; j < 8; j++) {
            mx0 = fmaxf(mx0, fmaxf(s[j][0], s[j][1]));
            mx1 = fmaxf(mx1, fmaxf(s[j][2], s[j][3]));
        }
        mx0 = fmaxf(mx0, __shfl_xor_sync(0xffffffffu, mx0, 1));
        mx0 = fmaxf(mx0, __shfl_xor_sync(0xffffffffu, mx0, 2));
        mx1 = fmaxf(mx1, __shfl_xor_sync(0xffffffffu, mx1, 1));
        mx1 = fmaxf(mx1, __shfl_xor_sync(0xffffffffu, mx1, 2));
        float nm0 = fmaxf(m0, mx0), nm1 = fmaxf(m1, mx1);
        float c0 = __expf(m0 - nm0), c1 = __expf(m1 - nm1);
        m0 = nm0; m1 = nm1;
        float rs0 = 0.f, rs1 = 0.f;
#pragma unroll
        for (int j = 0; j < 8; j++) {
            s[j][0] = __expf(s[j][0] - m0);
            s[j][1] = __expf(s[j][1] - m0);
            s[j][2] = __expf(s[j][2] - m1);
            s[j][3] = __expf(s[j][3] - m1);
            rs0 += s[j][0] + s[j][1];
            rs1 += s[j][2] + s[j][3];
        }
        rs0 += __shfl_xor_sync(0xffffffffu, rs0, 1);
        rs0 += __shfl_xor_sync(0xffffffffu, rs0, 2);
        rs1 += __shfl_xor_sync(0xffffffffu, rs1, 1);
        rs1 += __shfl_xor_sync(0xffffffffu, rs1, 2);
        l0 = l0 * c0 + rs0;
        l1 = l1 * c1 + rs1;
#pragma unroll
        for (int j = 0; j < 8; j++) {
            o[j][0] *= c0; o[j][1] *= c0;
            o[j][2] *= c1; o[j][3] *= c1;
        }

        // ---- store P (tf32) into KP; rows are warp-private
#pragma unroll
        for (int j = 0; j < 8; j++) {
            *(uint2*)&KP[(qw + ly) * AST + 8 * j + 2 * lx] =
                make_uint2(f2tf(s[j][0]), f2tf(s[j][1]));
            *(uint2*)&KP[(qw + ly + 8) * AST + 8 * j + 2 * lx] =
                make_uint2(f2tf(s[j][2]), f2tf(s[j][3]));
        }
        __syncwarp();      // P rows read only by this warp

        // ---- O += P V : k = keys, n = 64 dims
#pragma unroll
        for (int ks = 0; ks < 8; ks++) {
            uint32_t pa[4];
            int abase = (qw + ly) * AST + 8 * ks + lx;
            pa[0] = KP[abase];
            pa[1] = KP[abase + 8 * AST];
            pa[2] = KP[abase + 4];
            pa[3] = KP[abase + 8 * AST + 4];
#pragma unroll
            for (int j = 0; j < 8; j++) {
                uint32_t bf[2];
                int bbase = (8 * ks + lx) * AST + ly + 8 * j;
                bf[0] = Vs[bbase];
                bf[1] = Vs[bbase + 4 * AST];
                mma8(o[j], pa, bf);
            }
        }
        __syncthreads();   // done with KP(P)+Vs before next tile's loads
    }

    // ---- normalize + write
    float i0 = 1.f / l0, i1 = 1.f / l1;
#pragma unroll
    for (int j = 0; j < 8; j++) {
        *(float2*)(Og + (size_t)(qw + ly) * DD + 8 * j + 2 * lx) =
            make_float2(o[j][0] * i0, o[j][1] * i0);
        *(float2*)(Og + (size_t)(qw + ly + 8) * DD + 8 * j + 2 * lx) =
            make_float2(o[j][2] * i1, o[j][3] * i1);
    }
}

// ---------------------------------------------------------------------------
extern "C" void kernel_launch(void* const* d_in, const int* in_sizes, int n_in,
                              void* d_out, int out_size)
{
    const float* q  = (const float*)d_in[0];
    const float* k  = (const float*)d_in[1];
    const float* v  = (const float*)d_in[2];
    const float* Wq = (const float*)d_in[3];
    const float* Wk = (const float*)d_in[4];
    const float* Wv = (const float*)d_in[5];
    const float* Wo = (const float*)d_in[6];
    const float* bo = (const float*)d_in[7];
    float* out = (float*)d_out;

    void *pQ, *pK, *pV, *pAO;
    cudaGetSymbolAddress(&pQ,  g_Q);
    cudaGetSymbolAddress(&pK,  g_K);
    cudaGetSymbolAddress(&pV,  g_V);
    cudaGetSymbolAddress(&pAO, g_AO);

    dim3 gg(DD / 128, MM / 128);   // (8, 64)
    // scale 1/sqrt(D)=1/32 folded into Q projection
    gemm_mma<<<gg, 256>>>(q, Wq, (float*)pQ, nullptr, 0.03125f);
    gemm_mma<<<gg, 256>>>(k, Wk, (float*)pK, nullptr, 1.0f);
    gemm_mma<<<gg, 256>>>(v, Wv, (float*)pV, nullptr, 1.0f);

    dim3 ga(SS / 64, BB * HH);     // (32, 64)
    attn_mma<<<ga, 128>>>((const float*)pQ, (const float*)pK,
                          (const float*)pV, (float*)pAO);

    gemm_mma<<<gg, 256>>>((const float*)pAO, Wo, out, bo, 1.0f);
}

// round 12
// speedup vs baseline: 5.4108x; 1.2387x over previous
#include <cuda_runtime.h>
#include <cstdint>
#include <math.h>

#define BB 4
#define SS 2048
#define DD 1024
#define HH 16
#define HDIM 64
#define MM (BB*SS)   /* 8192 */

// Scratch (device globals — no allocations allowed)
__device__ float g_Q [BB*SS*DD];
__device__ float g_K [BB*SS*DD];
__device__ float g_V [BB*SS*DD];
__device__ float g_AO[BB*SS*DD];

// ---------------------------------------------------------------------------
// tf32 helpers (plain PTX ISA — no sm_103a-gated features)
// ---------------------------------------------------------------------------
static __device__ __forceinline__ uint32_t f2tf(float x) {
    uint32_t u;
    asm("cvt.rna.tf32.f32 %0, %1;" : "=r"(u) : "f"(x));
    return u;
}

static __device__ __forceinline__ void mma8(float* c, const uint32_t* a,
                                            const uint32_t* b) {
    asm volatile(
        "mma.sync.aligned.m16n8k8.row.col.f32.tf32.tf32.f32 "
        "{%0,%1,%2,%3}, {%4,%5,%6,%7}, {%8,%9}, {%0,%1,%2,%3};"
        : "+f"(c[0]), "+f"(c[1]), "+f"(c[2]), "+f"(c[3])
        : "r"(a[0]), "r"(a[1]), "r"(a[2]), "r"(a[3]), "r"(b[0]), "r"(b[1]));
}

// ---------------------------------------------------------------------------
// tf32 mma.sync GEMM: C[M,N] = alpha * A[M,K] * W[N,K]^T (+ bias)
// CTA 128x128, 256 threads (8 warps x 32x64 tiles), K-chunk 32.
// gridDim.z selects among up to 3 fused (A, W, C, alpha) problems.
// ---------------------------------------------------------------------------
#define LDA 36

__global__ __launch_bounds__(256) void gemm_mma(
    const float* __restrict__ A0, const float* __restrict__ W0, float* C0, float al0,
    const float* __restrict__ A1, const float* __restrict__ W1, float* C1, float al1,
    const float* __restrict__ A2, const float* __restrict__ W2, float* C2, float al2,
    const float* __restrict__ bias)
{
    __shared__ uint32_t As[128 * LDA];
    __shared__ uint32_t Ws[128 * LDA];

    const float* A; const float* W; float* C; float alpha;
    if (blockIdx.z == 0)      { A = A0; W = W0; C = C0; alpha = al0; }
    else if (blockIdx.z == 1) { A = A1; W = W1; C = C1; alpha = al1; }
    else                      { A = A2; W = W2; C = C2; alpha = al2; }

    const int tid  = threadIdx.x;
    const int w    = tid >> 5;
    const int lane = tid & 31;
    const int ly   = lane >> 2;
    const int lx   = lane & 3;
    const int m0   = blockIdx.y * 128;
    const int n0   = blockIdx.x * 128;
    const int wm   = (w & 3) * 32;
    const int wn   = (w >> 2) * 64;

    const int lrow = tid >> 3;
    const int lc4  = tid & 7;
    const float* Ap = A + (size_t)(m0 + lrow) * DD + lc4 * 4;
    const float* Wp = W + (size_t)(n0 + lrow) * DD + lc4 * 4;

    float acc[2][8][4];
#pragma unroll
    for (int i = 0; i < 2; i++)
#pragma unroll
        for (int j = 0; j < 8; j++)
#pragma unroll
            for (int r = 0; r < 4; r++) acc[i][j][r] = 0.f;

    float4 ra[4], rw[4];
#pragma unroll
    for (int i = 0; i < 4; i++) {
        ra[i] = *(const float4*)(Ap + (size_t)(32 * i) * DD);
        rw[i] = *(const float4*)(Wp + (size_t)(32 * i) * DD);
    }
#pragma unroll
    for (int i = 0; i < 4; i++) {
        uint32_t* pa = &As[(lrow + 32 * i) * LDA + lc4 * 4];
        pa[0] = f2tf(ra[i].x); pa[1] = f2tf(ra[i].y);
        pa[2] = f2tf(ra[i].z); pa[3] = f2tf(ra[i].w);
        uint32_t* pw = &Ws[(lrow + 32 * i) * LDA + lc4 * 4];
        pw[0] = f2tf(rw[i].x); pw[1] = f2tf(rw[i].y);
        pw[2] = f2tf(rw[i].z); pw[3] = f2tf(rw[i].w);
    }
    __syncthreads();

    for (int kc = 0; kc < DD / 32; kc++) {
        if (kc + 1 < DD / 32) {
            const float* Ap2 = Ap + (kc + 1) * 32;
            const float* Wp2 = Wp + (kc + 1) * 32;
#pragma unroll
            for (int i = 0; i < 4; i++) {
                ra[i] = *(const float4*)(Ap2 + (size_t)(32 * i) * DD);
                rw[i] = *(const float4*)(Wp2 + (size_t)(32 * i) * DD);
            }
        }

#pragma unroll
        for (int ks = 0; ks < 4; ks++) {
            const int k0 = ks * 8;
            uint32_t af[2][4], bf[8][2];
#pragma unroll
            for (int i = 0; i < 2; i++) {
                int base = (wm + i * 16 + ly) * LDA + k0 + lx;
                af[i][0] = As[base];
                af[i][1] = As[base + 8 * LDA];
                af[i][2] = As[base + 4];
                af[i][3] = As[base + 8 * LDA + 4];
            }
#pragma unroll
            for (int j = 0; j < 8; j++) {
                int base = (wn + j * 8 + ly) * LDA + k0 + lx;
                bf[j][0] = Ws[base];
                bf[j][1] = Ws[base + 4];
            }
#pragma unroll
            for (int i = 0; i < 2; i++)
#pragma unroll
                for (int j = 0; j < 8; j++)
                    mma8(acc[i][j], af[i], bf[j]);
        }
        __syncthreads();

        if (kc + 1 < DD / 32) {
#pragma unroll
            for (int i = 0; i < 4; i++) {
                uint32_t* pa = &As[(lrow + 32 * i) * LDA + lc4 * 4];
                pa[0] = f2tf(ra[i].x); pa[1] = f2tf(ra[i].y);
                pa[2] = f2tf(ra[i].z); pa[3] = f2tf(ra[i].w);
                uint32_t* pw = &Ws[(lrow + 32 * i) * LDA + lc4 * 4];
                pw[0] = f2tf(rw[i].x); pw[1] = f2tf(rw[i].y);
                pw[2] = f2tf(rw[i].z); pw[3] = f2tf(rw[i].w);
            }
            __syncthreads();
        }
    }

#pragma unroll
    for (int i = 0; i < 2; i++) {
        int row = m0 + wm + i * 16 + ly;
#pragma unroll
        for (int j = 0; j < 8; j++) {
            int col = n0 + wn + j * 8 + lx * 2;
            float b0 = bias ? bias[col]     : 0.f;
            float b1 = bias ? bias[col + 1] : 0.f;
            float2 v0 = make_float2(acc[i][j][0] * alpha + b0,
                                    acc[i][j][1] * alpha + b1);
            float2 v1 = make_float2(acc[i][j][2] * alpha + b0,
                                    acc[i][j][3] * alpha + b1);
            *(float2*)(C + (size_t)row * DD + col)       = v0;
            *(float2*)(C + (size_t)(row + 8) * DD + col) = v1;
        }
    }
}

// ---------------------------------------------------------------------------
// Flash-attention, tf32 mma.sync, 2x query blocking.
// One block = (b, h, 128-query tile). 4 warps x 32 queries (2 frag sets).
// smem: Ks (stride 76: row-frag conflict-free), Vs (stride 72: col-frag
// conflict-free), Ps 128 rows (stride 76: store + row-frag conflict-free).
// Every K/V b-fragment feeds 2 mmas. Scale folded into Q projection.
// ---------------------------------------------------------------------------
#define KST 76
#define VST 72
#define PST 76
#define SM_K  0
#define SM_V  (64 * KST)            /* 4864  */
#define SM_P  (SM_V + 64 * VST)     /* 9472  */
#define SM_WORDS (SM_P + 128 * PST) /* 19200 words = 76800 B */

__global__ __launch_bounds__(128) void attn_mma(
    const float* __restrict__ Q,
    const float* __restrict__ K,
    const float* __restrict__ V,
    float* __restrict__ O)
{
    extern __shared__ uint32_t sm[];
    uint32_t* Ks = sm + SM_K;
    uint32_t* Vs = sm + SM_V;
    uint32_t* Ps = sm + SM_P;

    const int tid  = threadIdx.x;
    const int w    = tid >> 5;
    const int lane = tid & 31;
    const int ly   = lane >> 2;         // 0..7
    const int lx   = lane & 3;          // 0..3
    const int qw   = w * 32;            // warp query offset in 128-tile
    const int qt   = blockIdx.x;        // 0..15
    const int bh   = blockIdx.y;        // 0..63
    const int b    = bh >> 4;
    const int h    = bh & 15;

    const float* Qg = Q + ((size_t)b * SS + qt * 128) * DD + h * HDIM;
    const float* Kg = K + (size_t)b * SS * DD + h * HDIM;
    const float* Vg = V + (size_t)b * SS * DD + h * HDIM;
    float*       Og = O + ((size_t)b * SS + qt * 128) * DD + h * HDIM;

    // ---- Q fragments: 2 sets x 8 k-slices, registers for whole kernel
    uint32_t aq[2][8][4];
#pragma unroll
    for (int u = 0; u < 2; u++)
#pragma unroll
        for (int ks = 0; ks < 8; ks++) {
            const float* qp = Qg + (size_t)(qw + 16 * u + ly) * DD + ks * 8 + lx;
            aq[u][ks][0] = f2tf(qp[0]);
            aq[u][ks][1] = f2tf(qp[(size_t)8 * DD]);
            aq[u][ks][2] = f2tf(qp[4]);
            aq[u][ks][3] = f2tf(qp[(size_t)8 * DD + 4]);
        }

    float o[2][8][4];
    float m[2][2], l[2][2];
#pragma unroll
    for (int u = 0; u < 2; u++) {
        m[u][0] = m[u][1] = -1e30f;
        l[u][0] = l[u][1] = 0.f;
#pragma unroll
        for (int j = 0; j < 8; j++)
#pragma unroll
            for (int r = 0; r < 4; r++) o[u][j][r] = 0.f;
    }

    for (int t = 0; t < SS / 64; t++) {
        // ---- load K,V tiles (64 keys x 64 dims), cvt to tf32 at store
#pragma unroll
        for (int it = 0; it < 8; it++) {
            int idx = it * 128 + tid;
            int c = idx >> 4, d4 = (idx & 15) << 2;
            float4 kv = *(const float4*)(Kg + (size_t)(t * 64 + c) * DD + d4);
            *(uint4*)&Ks[c * KST + d4] =
                make_uint4(f2tf(kv.x), f2tf(kv.y), f2tf(kv.z), f2tf(kv.w));
            float4 vv = *(const float4*)(Vg + (size_t)(t * 64 + c) * DD + d4);
            *(uint4*)&Vs[c * VST + d4] =
                make_uint4(f2tf(vv.x), f2tf(vv.y), f2tf(vv.z), f2tf(vv.w));
        }
        __syncthreads();

        // ---- S = Q K^T : each b-fragment feeds both query sets
        float s[2][8][4];
#pragma unroll
        for (int u = 0; u < 2; u++)
#pragma unroll
            for (int j = 0; j < 8; j++)
#pragma unroll
                for (int r = 0; r < 4; r++) s[u][j][r] = 0.f;

#pragma unroll
        for (int ks = 0; ks < 8; ks++) {
#pragma unroll
            for (int j = 0; j < 8; j++) {
                uint32_t bf[2];
                int base = (ly + 8 * j) * KST + 8 * ks + lx;
                bf[0] = Ks[base];
                bf[1] = Ks[base + 4];
                mma8(s[0][j], aq[0][ks], bf);
                mma8(s[1][j], aq[1][ks], bf);
            }
        }

        // ---- online softmax per query set (P buffer is separate from K)
#pragma unroll
        for (int u = 0; u < 2; u++) {
            float mx0 = -1e30f, mx1 = -1e30f;
#pragma unroll
            for (int j = 0; j < 8; j++) {
                mx0 = fmaxf(mx0, fmaxf(s[u][j][0], s[u][j][1]));
                mx1 = fmaxf(mx1, fmaxf(s[u][j][2], s[u][j][3]));
            }
            mx0 = fmaxf(mx0, __shfl_xor_sync(0xffffffffu, mx0, 1));
            mx0 = fmaxf(mx0, __shfl_xor_sync(0xffffffffu, mx0, 2));
            mx1 = fmaxf(mx1, __shfl_xor_sync(0xffffffffu, mx1, 1));
            mx1 = fmaxf(mx1, __shfl_xor_sync(0xffffffffu, mx1, 2));
            float nm0 = fmaxf(m[u][0], mx0), nm1 = fmaxf(m[u][1], mx1);
            float c0 = __expf(m[u][0] - nm0), c1 = __expf(m[u][1] - nm1);
            m[u][0] = nm0; m[u][1] = nm1;
            float rs0 = 0.f, rs1 = 0.f;
#pragma unroll
            for (int j = 0; j < 8; j++) {
                s[u][j][0] = __expf(s[u][j][0] - nm0);
                s[u][j][1] = __expf(s[u][j][1] - nm0);
                s[u][j][2] = __expf(s[u][j][2] - nm1);
                s[u][j][3] = __expf(s[u][j][3] - nm1);
                rs0 += s[u][j][0] + s[u][j][1];
                rs1 += s[u][j][2] + s[u][j][3];
            }
            rs0 += __shfl_xor_sync(0xffffffffu, rs0, 1);
            rs0 += __shfl_xor_sync(0xffffffffu, rs0, 2);
            rs1 += __shfl_xor_sync(0xffffffffu, rs1, 1);
            rs1 += __shfl_xor_sync(0xffffffffu, rs1, 2);
            l[u][0] = l[u][0] * c0 + rs0;
            l[u][1] = l[u][1] * c1 + rs1;
#pragma unroll
            for (int j = 0; j < 8; j++) {
                o[u][j][0] *= c0; o[u][j][1] *= c0;
                o[u][j][2] *= c1; o[u][j][3] *= c1;
                // store P rows (warp-private region of Ps)
                int r0 = qw + 16 * u + ly;
                *(uint2*)&Ps[r0 * PST + 8 * j + 2 * lx] =
                    make_uint2(f2tf(s[u][j][0]), f2tf(s[u][j][1]));
                *(uint2*)&Ps[(r0 + 8) * PST + 8 * j + 2 * lx] =
                    make_uint2(f2tf(s[u][j][2]), f2tf(s[u][j][3]));
            }
        }
        __syncwarp();      // P rows produced and consumed by this warp only

        // ---- O += P V : each V b-fragment feeds both query sets
#pragma unroll
        for (int ks = 0; ks < 8; ks++) {
            uint32_t pa[2][4];
#pragma unroll
            for (int u = 0; u < 2; u++) {
                int ab = (qw + 16 * u + ly) * PST + 8 * ks + lx;
                pa[u][0] = Ps[ab];
                pa[u][1] = Ps[ab + 8 * PST];
                pa[u][2] = Ps[ab + 4];
                pa[u][3] = Ps[ab + 8 * PST + 4];
            }
#pragma unroll
            for (int j = 0; j < 8; j++) {
                uint32_t bf[2];
                int bb = (8 * ks + lx) * VST + ly + 8 * j;
                bf[0] = Vs[bb];
                bf[1] = Vs[bb + 4 * VST];
                mma8(o[0][j], pa[0], bf);
                mma8(o[1][j], pa[1], bf);
            }
        }
        __syncthreads();   // all warps done with Ks/Vs before next tile load
    }

    // ---- normalize + write
#pragma unroll
    for (int u = 0; u < 2; u++) {
        float i0 = 1.f / l[u][0], i1 = 1.f / l[u][1];
        int r0 = qw + 16 * u + ly;
#pragma unroll
        for (int j = 0; j < 8; j++) {
            *(float2*)(Og + (size_t)r0 * DD + 8 * j + 2 * lx) =
                make_float2(o[u][j][0] * i0, o[u][j][1] * i0);
            *(float2*)(Og + (size_t)(r0 + 8) * DD + 8 * j + 2 * lx) =
                make_float2(o[u][j][2] * i1, o[u][j][3] * i1);
        }
    }
}

// ---------------------------------------------------------------------------
extern "C" void kernel_launch(void* const* d_in, const int* in_sizes, int n_in,
                              void* d_out, int out_size)
{
    const float* q  = (const float*)d_in[0];
    const float* k  = (const float*)d_in[1];
    const float* v  = (const float*)d_in[2];
    const float* Wq = (const float*)d_in[3];
    const float* Wk = (const float*)d_in[4];
    const float* Wv = (const float*)d_in[5];
    const float* Wo = (const float*)d_in[6];
    const float* bo = (const float*)d_in[7];
    float* out = (float*)d_out;

    void *pQ, *pK, *pV, *pAO;
    cudaGetSymbolAddress(&pQ,  g_Q);
    cudaGetSymbolAddress(&pK,  g_K);
    cudaGetSymbolAddress(&pV,  g_V);
    cudaGetSymbolAddress(&pAO, g_AO);

    static int init = 0;
    if (!init) {
        cudaFuncSetAttribute(attn_mma, cudaFuncAttributeMaxDynamicSharedMemorySize,
                             SM_WORDS * 4);
        init = 1;
    }

    // fused Q/K/V projections (scale 1/32 folded into Q)
    dim3 gg3(DD / 128, MM / 128, 3);
    gemm_mma<<<gg3, 256>>>(q, Wq, (float*)pQ, 0.03125f,
                           k, Wk, (float*)pK, 1.0f,
                           v, Wv, (float*)pV, 1.0f, nullptr);

    dim3 ga(SS / 128, BB * HH);    // (16, 64)
    attn_mma<<<ga, 128, SM_WORDS * 4>>>((const float*)pQ, (const float*)pK,
                                        (const float*)pV, (float*)pAO);

    dim3 gg(DD / 128, MM / 128, 1);
    gemm_mma<<<gg, 256>>>((const float*)pAO, Wo, out, 1.0f,
                          nullptr, nullptr, nullptr, 0.f,
                          nullptr, nullptr, nullptr, 0.f, bo);
}